// round 1
// baseline (speedup 1.0000x reference)
#include <cuda_runtime.h>

// Problem dims
constexpr int kB  = 16;
constexpr int kN  = 128;
constexpr int kC  = 512;
constexpr int kH  = 8;
constexpr int kR  = 17;
constexpr int kHD = 64;
constexpr int kBN = kB * kN;    // 2048
constexpr int kC2 = 2 * kC;     // 1024

// Scratch (device globals; no allocations allowed)
__device__ float g_q[kBN * kC];        // 4 MB
__device__ float g_y[kBN * kC2];       // 8 MB  (yk | yv interleaved per row)
__device__ float g_S[kB * kH * kN * kN]; // 8 MB
__device__ float g_W[kB * kH * kN * kN]; // 8 MB
__device__ float g_O[kBN * kC];        // 4 MB
__device__ int   g_mask_mode;          // 0=int32, 1=float32, 2=uint8

__device__ __forceinline__ float neg_inf() { return __int_as_float(0xFF800000); }

// ---------------------------------------------------------------------------
// Probe the mask buffer encoding. mask has 128*17 = 2176 elements.
// First 544 uint32 words (2176 bytes) are in-bounds under every encoding.
// ---------------------------------------------------------------------------
__global__ void mask_probe_kernel(const void* __restrict__ mask) {
    __shared__ int s_not_i32, s_not_f32;
    if (threadIdx.x == 0) { s_not_i32 = 0; s_not_f32 = 0; }
    __syncthreads();
    const unsigned int* w = (const unsigned int*)mask;
    int bad_i = 0, bad_f = 0;
    for (int i = threadIdx.x; i < 544; i += blockDim.x) {
        unsigned int v = w[i];
        if (v > 1u) bad_i = 1;
        if (v != 0u && v != 0x3F800000u) bad_f = 1;
    }
    if (bad_i) atomicOr(&s_not_i32, 1);
    if (bad_f) atomicOr(&s_not_f32, 1);
    __syncthreads();
    if (threadIdx.x == 0)
        g_mask_mode = (!s_not_i32) ? 0 : ((!s_not_f32) ? 1 : 2);
}

// ---------------------------------------------------------------------------
// SGEMM: C[M,Nc] = A[M,K] @ W[Nc,K]^T (+ bias[col]).
// Tiles 64x128x16, 256 threads, 4x8 per-thread microtile.
// ---------------------------------------------------------------------------
__global__ __launch_bounds__(256) void sgemm_nt_kernel(
    const float* __restrict__ A, const float* __restrict__ Wm,
    const float* __restrict__ bias, float* __restrict__ Cc,
    int M, int Nc, int K)
{
    constexpr int BM = 64, BNt = 128, BK = 16;
    __shared__ float As[BK][BM];
    __shared__ float Bs[BK][BNt];

    const int tid = threadIdx.x;
    const int tx = tid & 15;        // 16 cols of 8
    const int ty = tid >> 4;        // 16 rows of 4
    const int bm0 = blockIdx.y * BM;
    const int bn0 = blockIdx.x * BNt;

    float acc[4][8];
#pragma unroll
    for (int i = 0; i < 4; i++)
#pragma unroll
        for (int j = 0; j < 8; j++) acc[i][j] = 0.f;

    const int ar = tid >> 2;          // 0..63
    const int ac = (tid & 3) * 4;     // 0,4,8,12

    for (int k0 = 0; k0 < K; k0 += BK) {
        float4 av = *(const float4*)&A[(size_t)(bm0 + ar) * K + k0 + ac];
        As[ac + 0][ar] = av.x; As[ac + 1][ar] = av.y;
        As[ac + 2][ar] = av.z; As[ac + 3][ar] = av.w;
#pragma unroll
        for (int p = 0; p < 2; p++) {
            int f = tid + p * 256;
            int br = f >> 2;           // 0..127
            int bc = (f & 3) * 4;      // 0,4,8,12
            float4 bv = *(const float4*)&Wm[(size_t)(bn0 + br) * K + k0 + bc];
            Bs[bc + 0][br] = bv.x; Bs[bc + 1][br] = bv.y;
            Bs[bc + 2][br] = bv.z; Bs[bc + 3][br] = bv.w;
        }
        __syncthreads();
#pragma unroll
        for (int k = 0; k < BK; k++) {
            float4 a0 = *(const float4*)&As[k][ty * 4];
            float4 b0 = *(const float4*)&Bs[k][tx * 8];
            float4 b1 = *(const float4*)&Bs[k][tx * 8 + 4];
            float a[4]  = {a0.x, a0.y, a0.z, a0.w};
            float bb[8] = {b0.x, b0.y, b0.z, b0.w, b1.x, b1.y, b1.z, b1.w};
#pragma unroll
            for (int i = 0; i < 4; i++)
#pragma unroll
                for (int j = 0; j < 8; j++) acc[i][j] += a[i] * bb[j];
        }
        __syncthreads();
    }

    float4 bz = make_float4(0.f, 0.f, 0.f, 0.f);
    float4 bb0 = bias ? *(const float4*)&bias[bn0 + tx * 8]     : bz;
    float4 bb1 = bias ? *(const float4*)&bias[bn0 + tx * 8 + 4] : bz;
#pragma unroll
    for (int i = 0; i < 4; i++) {
        int row = bm0 + ty * 4 + i;
        float4 o0 = make_float4(acc[i][0] + bb0.x, acc[i][1] + bb0.y,
                                acc[i][2] + bb0.z, acc[i][3] + bb0.w);
        float4 o1 = make_float4(acc[i][4] + bb1.x, acc[i][5] + bb1.y,
                                acc[i][6] + bb1.z, acc[i][7] + bb1.w);
        *(float4*)&Cc[(size_t)row * Nc + bn0 + tx * 8]     = o0;
        *(float4*)&Cc[(size_t)row * Nc + bn0 + tx * 8 + 4] = o1;
    }
}

// ---------------------------------------------------------------------------
// S[b,h,n,m] = scale * sum_d q[b,n,h,d] * yk[b,m,h,d]
// One block per (b,h): 128x128x64. 256 threads, 8x8 microtile.
// ---------------------------------------------------------------------------
__global__ __launch_bounds__(256) void qk_kernel(
    const float* __restrict__ q, const float* __restrict__ y,
    float* __restrict__ S)
{
    const int bh = blockIdx.x;
    const int b = bh >> 3, h = bh & 7;
    __shared__ float qs[32][128];   // [d][n]
    __shared__ float ks[32][128];   // [d][m]
    const int tid = threadIdx.x;
    const int tx = tid & 15, ty = tid >> 4;

    float acc[8][8];
#pragma unroll
    for (int i = 0; i < 8; i++)
#pragma unroll
        for (int j = 0; j < 8; j++) acc[i][j] = 0.f;

    const float* qbase = q + (size_t)b * kN * kC  + h * kHD;
    const float* kbase = y + (size_t)b * kN * kC2 + h * kHD;

    for (int d0 = 0; d0 < kHD; d0 += 32) {
#pragma unroll
        for (int p = 0; p < 4; p++) {
            int f = tid + p * 256;       // 0..1023
            int n = f >> 3;              // 0..127
            int dd = (f & 7) * 4;        // 0..28
            float4 v = *(const float4*)&qbase[(size_t)n * kC + d0 + dd];
            qs[dd + 0][n] = v.x; qs[dd + 1][n] = v.y;
            qs[dd + 2][n] = v.z; qs[dd + 3][n] = v.w;
            float4 w = *(const float4*)&kbase[(size_t)n * kC2 + d0 + dd];
            ks[dd + 0][n] = w.x; ks[dd + 1][n] = w.y;
            ks[dd + 2][n] = w.z; ks[dd + 3][n] = w.w;
        }
        __syncthreads();
#pragma unroll
        for (int d = 0; d < 32; d++) {
            float a[8], bb[8];
            *(float4*)&a[0]  = *(const float4*)&qs[d][ty * 8];
            *(float4*)&a[4]  = *(const float4*)&qs[d][ty * 8 + 4];
            *(float4*)&bb[0] = *(const float4*)&ks[d][tx * 8];
            *(float4*)&bb[4] = *(const float4*)&ks[d][tx * 8 + 4];
#pragma unroll
            for (int i = 0; i < 8; i++)
#pragma unroll
                for (int j = 0; j < 8; j++) acc[i][j] += a[i] * bb[j];
        }
        __syncthreads();
    }

    const float scale = 0.125f;   // 64^-0.5
    float* Sbase = S + (size_t)bh * kN * kN;
#pragma unroll
    for (int i = 0; i < 8; i++) {
        int row = ty * 8 + i;
        float4 o0 = make_float4(acc[i][0] * scale, acc[i][1] * scale,
                                acc[i][2] * scale, acc[i][3] * scale);
        float4 o1 = make_float4(acc[i][4] * scale, acc[i][5] * scale,
                                acc[i][6] * scale, acc[i][7] * scale);
        *(float4*)&Sbase[(size_t)row * kN + tx * 8]     = o0;
        *(float4*)&Sbase[(size_t)row * kN + tx * 8 + 4] = o1;
    }
}

// ---------------------------------------------------------------------------
// Per (b,n): logits L[h,r] = sum_m A[n,m,r]*S[b,h,n,m] + rel_bias[h,r],
// masked softmax over r, then W[b,h,n,m] = sum_r P[h,r]*A[n,m,r].
// One block per (b,n), 256 threads.
// ---------------------------------------------------------------------------
__global__ __launch_bounds__(256) void att_kernel(
    const float* __restrict__ S, const float* __restrict__ assign,
    const void* __restrict__ mask, const float* __restrict__ rel_bias,
    float* __restrict__ Wout)
{
    const int bn = blockIdx.x;
    const int b = bn >> 7, n = bn & 127;
    __shared__ float As[kN * kR];    // [m][r], 2176
    __shared__ float Ss[kH * kN];    // [h][m], 1024
    __shared__ float Ls[kH][kR];
    __shared__ float Ps[kH][kR];
    const int tid = threadIdx.x;

    const float* arow = assign + (size_t)n * kN * kR;
    for (int i = tid; i < kN * kR; i += 256) As[i] = arow[i];
    for (int i = tid; i < kH * kN; i += 256) {
        int h = i >> 7, m = i & 127;
        Ss[i] = S[(((size_t)(b * kH + h)) * kN + n) * kN + m];
    }
    __syncthreads();

    if (tid < kH * kR) {
        int h = tid / kR, r = tid % kR;
        float acc = 0.f;
#pragma unroll 4
        for (int m = 0; m < kN; m++) acc += As[m * kR + r] * Ss[h * kN + m];
        acc += rel_bias[h * kR + r];
        int mode = g_mask_mode;
        int idx = n * kR + r;
        bool msk;
        if (mode == 0)      msk = ((const int*)mask)[idx] != 0;
        else if (mode == 1) msk = ((const float*)mask)[idx] != 0.f;
        else                msk = ((const unsigned char*)mask)[idx] != 0;
        Ls[h][r] = msk ? neg_inf() : acc;
    }
    __syncthreads();

    if (tid < kH) {
        int h = tid;
        float mx = neg_inf();
#pragma unroll
        for (int r = 0; r < kR; r++) mx = fmaxf(mx, Ls[h][r]);
        float s = 0.f;
#pragma unroll
        for (int r = 0; r < kR; r++) { float e = __expf(Ls[h][r] - mx); Ps[h][r] = e; s += e; }
        float inv = 1.f / s;
#pragma unroll
        for (int r = 0; r < kR; r++) Ps[h][r] *= inv;
    }
    __syncthreads();

    for (int i = tid; i < kH * kN; i += 256) {
        int h = i >> 7, m = i & 127;
        float acc = 0.f;
#pragma unroll
        for (int r = 0; r < kR; r++) acc += Ps[h][r] * As[m * kR + r];
        Wout[(((size_t)(b * kH + h)) * kN + n) * kN + m] = acc;
    }
}

// ---------------------------------------------------------------------------
// O[b,n,h,d] = sum_m W[b,h,n,m] * yv[b,m,h,d]
// One block per (b,h): 128x64x128. 256 threads, 8x4 microtile.
// ---------------------------------------------------------------------------
__global__ __launch_bounds__(256) void av_kernel(
    const float* __restrict__ Wg, const float* __restrict__ y,
    float* __restrict__ O)
{
    const int bh = blockIdx.x;
    const int b = bh >> 3, h = bh & 7;
    __shared__ float ws[32][128];   // [m][n]
    __shared__ float vs[32][64];    // [m][d]
    const int tid = threadIdx.x;
    const int tx = tid & 15, ty = tid >> 4;

    float acc[8][4];
#pragma unroll
    for (int i = 0; i < 8; i++)
#pragma unroll
        for (int j = 0; j < 4; j++) acc[i][j] = 0.f;

    const float* Wb = Wg + (size_t)bh * kN * kN;
    const float* vbase = y + (size_t)b * kN * kC2 + kC + h * kHD;

    for (int m0 = 0; m0 < kN; m0 += 32) {
#pragma unroll
        for (int p = 0; p < 4; p++) {
            int f = tid + p * 256;       // 0..1023
            int nrow = f >> 3;           // 0..127
            int mc = (f & 7) * 4;        // 0..28
            float4 v = *(const float4*)&Wb[(size_t)nrow * kN + m0 + mc];
            ws[mc + 0][nrow] = v.x; ws[mc + 1][nrow] = v.y;
            ws[mc + 2][nrow] = v.z; ws[mc + 3][nrow] = v.w;
        }
#pragma unroll
        for (int p = 0; p < 2; p++) {
            int f = tid + p * 256;       // 0..511
            int mrow = f >> 4;           // 0..31
            int dd = (f & 15) * 4;       // 0..60
            float4 v = *(const float4*)&vbase[(size_t)(m0 + mrow) * kC2 + dd];
            *(float4*)&vs[mrow][dd] = v;
        }
        __syncthreads();
#pragma unroll
        for (int k = 0; k < 32; k++) {
            float a[8], bb[4];
            *(float4*)&a[0]  = *(const float4*)&ws[k][ty * 8];
            *(float4*)&a[4]  = *(const float4*)&ws[k][ty * 8 + 4];
            *(float4*)&bb[0] = *(const float4*)&vs[k][tx * 4];
#pragma unroll
            for (int i = 0; i < 8; i++)
#pragma unroll
                for (int j = 0; j < 4; j++) acc[i][j] += a[i] * bb[j];
        }
        __syncthreads();
    }

#pragma unroll
    for (int i = 0; i < 8; i++) {
        int n = ty * 8 + i;
        float4 o = make_float4(acc[i][0], acc[i][1], acc[i][2], acc[i][3]);
        *(float4*)&O[((size_t)(b * kN + n)) * kC + h * kHD + tx * 4] = o;
    }
}

// ---------------------------------------------------------------------------
extern "C" void kernel_launch(void* const* d_in, const int* in_sizes, int n_in,
                              void* d_out, int out_size)
{
    const float* x        = (const float*)d_in[0];
    const float* assign   = (const float*)d_in[1];
    const void*  mask     = d_in[2];
    const float* q_w      = (const float*)d_in[3];
    const float* kv_w     = (const float*)d_in[4];
    const float* rel_bias = (const float*)d_in[5];
    const float* proj_w   = (const float*)d_in[6];
    const float* proj_b   = (const float*)d_in[7];

    float *q, *y, *S, *Wg, *O;
    cudaGetSymbolAddress((void**)&q,  g_q);
    cudaGetSymbolAddress((void**)&y,  g_y);
    cudaGetSymbolAddress((void**)&S,  g_S);
    cudaGetSymbolAddress((void**)&Wg, g_W);
    cudaGetSymbolAddress((void**)&O,  g_O);

    mask_probe_kernel<<<1, 256>>>(mask);

    // q = x @ q_w^T   (2048 x 512 x 512)
    sgemm_nt_kernel<<<dim3(kC / 128, kBN / 64), 256>>>(x, q_w, nullptr, q, kBN, kC, kC);
    // y = x @ kv_w^T  (2048 x 1024 x 512)
    sgemm_nt_kernel<<<dim3(kC2 / 128, kBN / 64), 256>>>(x, kv_w, nullptr, y, kBN, kC2, kC);
    // S[b,h] = scale * q_bh @ yk_bh^T
    qk_kernel<<<kB * kH, 256>>>(q, y, S);
    // logits + masked softmax + W = P @ A
    att_kernel<<<kB * kN, 256>>>(S, assign, mask, rel_bias, Wg);
    // O[b,h] = W_bh @ yv_bh
    av_kernel<<<kB * kH, 256>>>(Wg, y, O);
    // out = O @ proj_w^T + proj_b
    sgemm_nt_kernel<<<dim3(kC / 128, kBN / 64), 256>>>(O, proj_w, proj_b,
                                                       (float*)d_out, kBN, kC, kC);
}

// round 3
// speedup vs baseline: 1.6798x; 1.6798x over previous
#include <cuda_runtime.h>
#include <cuda_bf16.h>
#include <cstdint>

// Problem dims
constexpr int kB  = 16;
constexpr int kN  = 128;
constexpr int kC  = 512;
constexpr int kH  = 8;
constexpr int kR  = 17;
constexpr int kHD = 64;
constexpr int kBN = kB * kN;    // 2048
constexpr int kC2 = 2 * kC;     // 1024
constexpr int kKp = 3 * kC;     // 1536 split-K' (hi|lo|hi)
constexpr int kKpB = kKp * 2;   // 3072 bytes per row
constexpr int NIT = kKp / 32;   // 48 K-iterations of 32

// Scratch (device globals; no allocations allowed)
__device__ float g_q[kBN * kC];          // 4 MB
__device__ float g_y[kBN * kC2];         // 8 MB  (yk | yv per row)
__device__ float g_S[kB * kH * kN * kN]; // 8 MB
__device__ float g_W[kB * kH * kN * kN]; // 8 MB
__device__ float g_O[kBN * kC];          // 4 MB
__device__ int   g_mask_mode;
__device__ __nv_bfloat16 g_Ax[kBN * kKp];    // x    hi|lo|hi
__device__ __nv_bfloat16 g_Bqkv[kKp * kKp];  // [q_w;kv_w] hi|hi|lo
__device__ __nv_bfloat16 g_Bproj[kC * kKp];  // proj_w     hi|hi|lo
__device__ __nv_bfloat16 g_AO[kBN * kKp];    // O    hi|lo|hi

__device__ __forceinline__ float neg_inf() { return __int_as_float(0xFF800000); }

// ===================== baseline-PTX helpers (compute_103 safe) ==============
__device__ __forceinline__ uint32_t smem_u32(const void* p) {
    uint32_t a;
    asm("{ .reg .u64 t; cvta.to.shared.u64 t, %1; cvt.u32.u64 %0, t; }"
        : "=r"(a) : "l"(p));
    return a;
}
__device__ __forceinline__ void cp_async16(uint32_t saddr, const void* gaddr) {
    asm volatile("cp.async.cg.shared.global [%0], [%1], 16;"
                 :: "r"(saddr), "l"(gaddr) : "memory");
}
__device__ __forceinline__ void cp_commit() {
    asm volatile("cp.async.commit_group;" ::: "memory");
}
__device__ __forceinline__ void cp_wait0() {
    asm volatile("cp.async.wait_group 0;" ::: "memory");
}
__device__ __forceinline__ void ldsm_x4(uint32_t* r, uint32_t addr) {
    asm volatile("ldmatrix.sync.aligned.m8n8.x4.shared.b16 {%0,%1,%2,%3}, [%4];"
                 : "=r"(r[0]), "=r"(r[1]), "=r"(r[2]), "=r"(r[3]) : "r"(addr));
}
__device__ __forceinline__ void mma16816(float* d, const uint32_t* a, const uint32_t* b) {
    asm volatile("mma.sync.aligned.m16n8k16.row.col.f32.bf16.bf16.f32 "
                 "{%0,%1,%2,%3}, {%4,%5,%6,%7}, {%8,%9}, {%0,%1,%2,%3};"
                 : "+f"(d[0]), "+f"(d[1]), "+f"(d[2]), "+f"(d[3])
                 : "r"(a[0]), "r"(a[1]), "r"(a[2]), "r"(a[3]),
                   "r"(b[0]), "r"(b[1]));
}

// ===================== mask probe =====================
__global__ void mask_probe_kernel(const void* __restrict__ mask) {
    __shared__ int s_not_i32, s_not_f32;
    if (threadIdx.x == 0) { s_not_i32 = 0; s_not_f32 = 0; }
    __syncthreads();
    const unsigned int* w = (const unsigned int*)mask;
    int bad_i = 0, bad_f = 0;
    for (int i = threadIdx.x; i < 544; i += blockDim.x) {
        unsigned int v = w[i];
        if (v > 1u) bad_i = 1;
        if (v != 0u && v != 0x3F800000u) bad_f = 1;
    }
    if (bad_i) atomicOr(&s_not_i32, 1);
    if (bad_f) atomicOr(&s_not_f32, 1);
    __syncthreads();
    if (threadIdx.x == 0)
        g_mask_mode = (!s_not_i32) ? 0 : ((!s_not_f32) ? 1 : 2);
}

// ===================== hi/lo split converters =====================
// A-side (activations): [hi | lo | hi] along K'
__global__ void convert_a_kernel(const float* __restrict__ src,
                                 __nv_bfloat16* __restrict__ dst) {
    int row = blockIdx.x;
    const float* s = src + (size_t)row * kC;
    __nv_bfloat16* d = dst + (size_t)row * kKp;
    for (int j = threadIdx.x; j < kC; j += blockDim.x) {
        float v = s[j];
        __nv_bfloat16 hi = __float2bfloat16(v);
        __nv_bfloat16 lo = __float2bfloat16(v - __bfloat162float(hi));
        d[j] = hi; d[kC + j] = lo; d[2 * kC + j] = hi;
    }
}
// B-side (weights): [hi | hi | lo] along K'
__global__ void convert_b_kernel(const float* __restrict__ src,
                                 __nv_bfloat16* __restrict__ dst) {
    int row = blockIdx.x;
    const float* s = src + (size_t)row * kC;
    __nv_bfloat16* d = dst + (size_t)row * kKp;
    for (int j = threadIdx.x; j < kC; j += blockDim.x) {
        float v = s[j];
        __nv_bfloat16 hi = __float2bfloat16(v);
        __nv_bfloat16 lo = __float2bfloat16(v - __bfloat162float(hi));
        d[j] = hi; d[kC + j] = hi; d[2 * kC + j] = lo;
    }
}

// ===================== mma.sync bf16 split-K GEMM =====================
// C[128*gy rows, 128*gx cols] = A @ B^T, A[M,1536], B[N,1536], both K-contig.
// Output col c -> C0 (ld0) if c < split else C1 at col c-split (ld1).
// SMEM per stage: A 8KB | B 8KB. 16B-chunk swizzle: chunk' = chunk ^ (row&3).
__global__ __launch_bounds__(256) void mma_gemm_kernel(
    const __nv_bfloat16* __restrict__ A,
    const __nv_bfloat16* __restrict__ Bw,
    float* __restrict__ C0, float* __restrict__ C1,
    const float* __restrict__ bias,
    int split, int ld0, int ld1)
{
    __shared__ __align__(16) char smem[2][16384];
    const int tid = threadIdx.x;
    const int wid = tid >> 5, lane = tid & 31;
    const int m0 = blockIdx.y * 128, n0 = blockIdx.x * 128;
    const int warp_m = wid >> 1, warp_n = wid & 1;

    const char* Ag = (const char*)A  + (size_t)m0 * kKpB;
    const char* Bg = (const char*)Bw + (size_t)n0 * kKpB;

    // loader: id in [0,512): r = id>>2 (0..127), c4 = id&3 (16B chunk of 64B row)
    const int lr = tid >> 2, lc = tid & 3;
    const uint32_t lso = (uint32_t)(lr * 64 + ((lc ^ (lr & 3)) << 4));
    const uint32_t lso2 = (uint32_t)((lr + 64) * 64 + ((lc ^ ((lr + 64) & 3)) << 4));

    uint32_t sbase = smem_u32(&smem[0][0]);

    auto stage_load = [&](int st, int k0b) {
        uint32_t sA = sbase + st * 16384;
        uint32_t sB = sA + 8192;
        const char* a0 = Ag + (size_t)lr * kKpB + k0b + lc * 16;
        const char* b0 = Bg + (size_t)lr * kKpB + k0b + lc * 16;
        cp_async16(sA + lso,  a0);
        cp_async16(sB + lso,  b0);
        cp_async16(sA + lso2, a0 + (size_t)64 * kKpB);
        cp_async16(sB + lso2, b0 + (size_t)64 * kKpB);
    };

    float acc[2][8][4];
#pragma unroll
    for (int i = 0; i < 2; i++)
#pragma unroll
        for (int j = 0; j < 8; j++)
#pragma unroll
            for (int t = 0; t < 4; t++) acc[i][j][t] = 0.f;

    stage_load(0, 0);
    cp_commit();

    // precompute ldmatrix swizzled offsets (row-dependent part)
    const int a_row = warp_m * 32 + (lane & 15);            // + i*16
    const int a_chsel = lane >> 4;                           // 0/1 within k16
    const int b_mi = lane >> 3;
    const int b_row = warp_n * 64 + ((b_mi >> 1) << 3) + (lane & 7);  // + g*16
    const int b_chsel = b_mi & 1;

    for (int it = 0; it < NIT; it++) {
        cp_wait0();
        __syncthreads();
        if (it + 1 < NIT) { stage_load((it + 1) & 1, (it + 1) * 64); cp_commit(); }

        const uint32_t sA = sbase + (it & 1) * 16384;
        const uint32_t sB = sA + 8192;
#pragma unroll
        for (int kk = 0; kk < 2; kk++) {
            uint32_t a[2][4];
#pragma unroll
            for (int i = 0; i < 2; i++) {
                int r = a_row + i * 16;
                int ch = 2 * kk + a_chsel;
                ldsm_x4(a[i], sA + r * 64 + ((ch ^ (r & 3)) << 4));
            }
            uint32_t b[8][2];
#pragma unroll
            for (int g = 0; g < 4; g++) {
                int r = b_row + g * 16;
                int ch = 2 * kk + b_chsel;
                uint32_t rr[4];
                ldsm_x4(rr, sB + r * 64 + ((ch ^ (r & 3)) << 4));
                b[2 * g][0] = rr[0]; b[2 * g][1] = rr[1];
                b[2 * g + 1][0] = rr[2]; b[2 * g + 1][1] = rr[3];
            }
#pragma unroll
            for (int i = 0; i < 2; i++)
#pragma unroll
                for (int j = 0; j < 8; j++)
                    mma16816(acc[i][j], a[i], b[j]);
        }
        __syncthreads();
    }

    // epilogue: direct global stores (float2), optional bias, split columns
    const int gq = lane >> 2, t4 = lane & 3;
#pragma unroll
    for (int i = 0; i < 2; i++) {
#pragma unroll
        for (int j = 0; j < 8; j++) {
            int colg = n0 + warp_n * 64 + j * 8 + t4 * 2;
            float bz0 = bias ? bias[colg]     : 0.f;
            float bz1 = bias ? bias[colg + 1] : 0.f;
            float* Cc; int ldc, cc;
            if (colg < split) { Cc = C0; ldc = ld0; cc = colg; }
            else              { Cc = C1; ldc = ld1; cc = colg - split; }
            int row0 = m0 + warp_m * 32 + i * 16 + gq;
            float2 v0 = make_float2(acc[i][j][0] + bz0, acc[i][j][1] + bz1);
            float2 v1 = make_float2(acc[i][j][2] + bz0, acc[i][j][3] + bz1);
            *(float2*)&Cc[(size_t)row0 * ldc + cc]       = v0;
            *(float2*)&Cc[(size_t)(row0 + 8) * ldc + cc] = v1;
        }
    }
}

// ===================== qk: S[b,h,n,m] = scale * q·yk =====================
__global__ __launch_bounds__(256) void qk_kernel(
    const float* __restrict__ q, const float* __restrict__ y,
    float* __restrict__ S)
{
    const int bh = blockIdx.x;
    const int b = bh >> 3, h = bh & 7;
    __shared__ float qs[32][128];
    __shared__ float ks[32][128];
    const int tid = threadIdx.x;
    const int tx = tid & 15, ty = tid >> 4;

    float acc[8][8];
#pragma unroll
    for (int i = 0; i < 8; i++)
#pragma unroll
        for (int j = 0; j < 8; j++) acc[i][j] = 0.f;

    const float* qbase = q + (size_t)b * kN * kC  + h * kHD;
    const float* kbase = y + (size_t)b * kN * kC2 + h * kHD;

    for (int d0 = 0; d0 < kHD; d0 += 32) {
#pragma unroll
        for (int p = 0; p < 4; p++) {
            int f = tid + p * 256;
            int n = f >> 3;
            int dd = (f & 7) * 4;
            float4 v = *(const float4*)&qbase[(size_t)n * kC + d0 + dd];
            qs[dd + 0][n] = v.x; qs[dd + 1][n] = v.y;
            qs[dd + 2][n] = v.z; qs[dd + 3][n] = v.w;
            float4 w = *(const float4*)&kbase[(size_t)n * kC2 + d0 + dd];
            ks[dd + 0][n] = w.x; ks[dd + 1][n] = w.y;
            ks[dd + 2][n] = w.z; ks[dd + 3][n] = w.w;
        }
        __syncthreads();
#pragma unroll
        for (int d = 0; d < 32; d++) {
            float a[8], bb[8];
            *(float4*)&a[0]  = *(const float4*)&qs[d][ty * 8];
            *(float4*)&a[4]  = *(const float4*)&qs[d][ty * 8 + 4];
            *(float4*)&bb[0] = *(const float4*)&ks[d][tx * 8];
            *(float4*)&bb[4] = *(const float4*)&ks[d][tx * 8 + 4];
#pragma unroll
            for (int i = 0; i < 8; i++)
#pragma unroll
                for (int j = 0; j < 8; j++) acc[i][j] += a[i] * bb[j];
        }
        __syncthreads();
    }

    const float scale = 0.125f;
    float* Sbase = S + (size_t)bh * kN * kN;
#pragma unroll
    for (int i = 0; i < 8; i++) {
        int row = ty * 8 + i;
        float4 o0 = make_float4(acc[i][0] * scale, acc[i][1] * scale,
                                acc[i][2] * scale, acc[i][3] * scale);
        float4 o1 = make_float4(acc[i][4] * scale, acc[i][5] * scale,
                                acc[i][6] * scale, acc[i][7] * scale);
        *(float4*)&Sbase[(size_t)row * kN + tx * 8]     = o0;
        *(float4*)&Sbase[(size_t)row * kN + tx * 8 + 4] = o1;
    }
}

// ===================== att: logits + softmax + W = P@A =====================
__global__ __launch_bounds__(256) void att_kernel(
    const float* __restrict__ S, const float* __restrict__ assign,
    const void* __restrict__ mask, const float* __restrict__ rel_bias,
    float* __restrict__ Wout)
{
    const int bn = blockIdx.x;
    const int b = bn >> 7, n = bn & 127;
    __shared__ float As[kN * kR];
    __shared__ float Ss[kH * kN];
    __shared__ float Ls[kH][kR];
    __shared__ float Ps[kH][kR];
    const int tid = threadIdx.x;

    const float* arow = assign + (size_t)n * kN * kR;
    for (int i = tid; i < kN * kR; i += 256) As[i] = arow[i];
    for (int i = tid; i < kH * kN; i += 256) {
        int h = i >> 7, m = i & 127;
        Ss[i] = S[(((size_t)(b * kH + h)) * kN + n) * kN + m];
    }
    __syncthreads();

    if (tid < kH * kR) {
        int h = tid / kR, r = tid % kR;
        float acc = 0.f;
#pragma unroll 4
        for (int m = 0; m < kN; m++) acc += As[m * kR + r] * Ss[h * kN + m];
        acc += rel_bias[h * kR + r];
        int mode = g_mask_mode;
        int idx = n * kR + r;
        bool msk;
        if (mode == 0)      msk = ((const int*)mask)[idx] != 0;
        else if (mode == 1) msk = ((const float*)mask)[idx] != 0.f;
        else                msk = ((const unsigned char*)mask)[idx] != 0;
        Ls[h][r] = msk ? neg_inf() : acc;
    }
    __syncthreads();

    if (tid < kH) {
        int h = tid;
        float mx = neg_inf();
#pragma unroll
        for (int r = 0; r < kR; r++) mx = fmaxf(mx, Ls[h][r]);
        float s = 0.f;
#pragma unroll
        for (int r = 0; r < kR; r++) { float e = __expf(Ls[h][r] - mx); Ps[h][r] = e; s += e; }
        float inv = 1.f / s;
#pragma unroll
        for (int r = 0; r < kR; r++) Ps[h][r] *= inv;
    }
    __syncthreads();

    for (int i = tid; i < kH * kN; i += 256) {
        int h = i >> 7, m = i & 127;
        float acc = 0.f;
#pragma unroll
        for (int r = 0; r < kR; r++) acc += Ps[h][r] * As[m * kR + r];
        Wout[(((size_t)(b * kH + h)) * kN + n) * kN + m] = acc;
    }
}

// ===================== av: O[b,n,h,d] = W @ yv =====================
__global__ __launch_bounds__(256) void av_kernel(
    const float* __restrict__ Wg, const float* __restrict__ y,
    float* __restrict__ O)
{
    const int bh = blockIdx.x;
    const int b = bh >> 3, h = bh & 7;
    __shared__ float ws[32][128];
    __shared__ float vs[32][64];
    const int tid = threadIdx.x;
    const int tx = tid & 15, ty = tid >> 4;

    float acc[8][4];
#pragma unroll
    for (int i = 0; i < 8; i++)
#pragma unroll
        for (int j = 0; j < 4; j++) acc[i][j] = 0.f;

    const float* Wb = Wg + (size_t)bh * kN * kN;
    const float* vbase = y + (size_t)b * kN * kC2 + kC + h * kHD;

    for (int m0 = 0; m0 < kN; m0 += 32) {
#pragma unroll
        for (int p = 0; p < 4; p++) {
            int f = tid + p * 256;
            int nrow = f >> 3;
            int mc = (f & 7) * 4;
            float4 v = *(const float4*)&Wb[(size_t)nrow * kN + m0 + mc];
            ws[mc + 0][nrow] = v.x; ws[mc + 1][nrow] = v.y;
            ws[mc + 2][nrow] = v.z; ws[mc + 3][nrow] = v.w;
        }
#pragma unroll
        for (int p = 0; p < 2; p++) {
            int f = tid + p * 256;
            int mrow = f >> 4;
            int dd = (f & 15) * 4;
            float4 v = *(const float4*)&vbase[(size_t)(m0 + mrow) * kC2 + dd];
            *(float4*)&vs[mrow][dd] = v;
        }
        __syncthreads();
#pragma unroll
        for (int k = 0; k < 32; k++) {
            float a[8], bb[4];
            *(float4*)&a[0]  = *(const float4*)&ws[k][ty * 8];
            *(float4*)&a[4]  = *(const float4*)&ws[k][ty * 8 + 4];
            *(float4*)&bb[0] = *(const float4*)&vs[k][tx * 4];
#pragma unroll
            for (int i = 0; i < 8; i++)
#pragma unroll
                for (int j = 0; j < 4; j++) acc[i][j] += a[i] * bb[j];
        }
        __syncthreads();
    }

#pragma unroll
    for (int i = 0; i < 8; i++) {
        int n = ty * 8 + i;
        float4 o = make_float4(acc[i][0], acc[i][1], acc[i][2], acc[i][3]);
        *(float4*)&O[((size_t)(b * kN + n)) * kC + h * kHD + tx * 4] = o;
    }
}

// ===================== launch =====================
extern "C" void kernel_launch(void* const* d_in, const int* in_sizes, int n_in,
                              void* d_out, int out_size)
{
    const float* x        = (const float*)d_in[0];
    const float* assign   = (const float*)d_in[1];
    const void*  mask     = d_in[2];
    const float* q_w      = (const float*)d_in[3];
    const float* kv_w     = (const float*)d_in[4];
    const float* rel_bias = (const float*)d_in[5];
    const float* proj_w   = (const float*)d_in[6];
    const float* proj_b   = (const float*)d_in[7];

    float *q, *y, *S, *Wg, *O;
    __nv_bfloat16 *Ax, *Bqkv, *Bproj, *AO;
    cudaGetSymbolAddress((void**)&q,  g_q);
    cudaGetSymbolAddress((void**)&y,  g_y);
    cudaGetSymbolAddress((void**)&S,  g_S);
    cudaGetSymbolAddress((void**)&Wg, g_W);
    cudaGetSymbolAddress((void**)&O,  g_O);
    cudaGetSymbolAddress((void**)&Ax,    g_Ax);
    cudaGetSymbolAddress((void**)&Bqkv,  g_Bqkv);
    cudaGetSymbolAddress((void**)&Bproj, g_Bproj);
    cudaGetSymbolAddress((void**)&AO,    g_AO);

    mask_probe_kernel<<<1, 256>>>(mask);

    // bf16 hi/lo splits
    convert_a_kernel<<<kBN, 128>>>(x, Ax);
    convert_b_kernel<<<kC,  128>>>(q_w,  Bqkv);
    convert_b_kernel<<<kC2, 128>>>(kv_w, Bqkv + (size_t)kC * kKp);
    convert_b_kernel<<<kC,  128>>>(proj_w, Bproj);

    // fused q/kv projection: [2048 x 1536] = Ax @ Bqkv^T ; cols<512 -> q, else y
    mma_gemm_kernel<<<dim3(12, 16), 256>>>(Ax, Bqkv, q, y, nullptr, kC, kC, kC2);

    qk_kernel<<<kB * kH, 256>>>(q, y, S);
    att_kernel<<<kB * kN, 256>>>(S, assign, mask, rel_bias, Wg);
    av_kernel<<<kB * kH, 256>>>(Wg, y, O);

    // out-proj: [2048 x 512] = AO @ Bproj^T + bias
    convert_a_kernel<<<kBN, 128>>>(O, AO);
    mma_gemm_kernel<<<dim3(4, 16), 256>>>(AO, Bproj, (float*)d_out, (float*)d_out,
                                          proj_b, 1 << 30, kC, kC);
}

// round 4
// speedup vs baseline: 1.7418x; 1.0369x over previous
#include <cuda_runtime.h>
#include <cuda_bf16.h>
#include <cstdint>

// Problem dims
constexpr int kB  = 16;
constexpr int kN  = 128;
constexpr int kC  = 512;
constexpr int kH  = 8;
constexpr int kR  = 17;
constexpr int kHD = 64;
constexpr int kBN = kB * kN;    // 2048
constexpr int kKp = 3 * kC;     // 1536 split-K'
constexpr int kKq = 3 * kHD;    // 192 split-K' for qk

// Scratch (device globals; no allocations allowed)
__device__ float g_S[kB * kH * kN * kN]; // 8 MB
__device__ float g_W[kB * kH * kN * kN]; // 8 MB
__device__ float g_O[kBN * kC];          // 4 MB
__device__ float g_yv[kBN * kC];         // 4 MB  [b*n][h*d]
__device__ int   g_mask_mode;
__device__ __nv_bfloat16 g_Ax[kBN * kKp];        // x hi|lo|hi
__device__ __nv_bfloat16 g_Bqkv[kKp * kKp];      // [q_w;kv_w] hi|hi|lo
__device__ __nv_bfloat16 g_Bproj[kC * kKp];      // proj_w hi|hi|lo
__device__ __nv_bfloat16 g_AO[kBN * kKp];        // O hi|lo|hi
__device__ __nv_bfloat16 g_qbf[kB * kH * kN * kKq]; // q  hi|lo|hi per (b,h)
__device__ __nv_bfloat16 g_kbf[kB * kH * kN * kKq]; // k  hi|hi|lo per (b,h)

__device__ __forceinline__ float neg_inf() { return __int_as_float(0xFF800000); }

// ===================== baseline-PTX helpers =====================
__device__ __forceinline__ uint32_t smem_u32(const void* p) {
    uint32_t a;
    asm("{ .reg .u64 t; cvta.to.shared.u64 t, %1; cvt.u32.u64 %0, t; }"
        : "=r"(a) : "l"(p));
    return a;
}
__device__ __forceinline__ void cp_async16(uint32_t saddr, const void* gaddr) {
    asm volatile("cp.async.cg.shared.global [%0], [%1], 16;"
                 :: "r"(saddr), "l"(gaddr) : "memory");
}
__device__ __forceinline__ void cp_commit() {
    asm volatile("cp.async.commit_group;" ::: "memory");
}
__device__ __forceinline__ void cp_wait0() {
    asm volatile("cp.async.wait_group 0;" ::: "memory");
}
__device__ __forceinline__ void ldsm_x4(uint32_t* r, uint32_t addr) {
    asm volatile("ldmatrix.sync.aligned.m8n8.x4.shared.b16 {%0,%1,%2,%3}, [%4];"
                 : "=r"(r[0]), "=r"(r[1]), "=r"(r[2]), "=r"(r[3]) : "r"(addr));
}
__device__ __forceinline__ void mma16816(float* d, const uint32_t* a, const uint32_t* b) {
    asm volatile("mma.sync.aligned.m16n8k16.row.col.f32.bf16.bf16.f32 "
                 "{%0,%1,%2,%3}, {%4,%5,%6,%7}, {%8,%9}, {%0,%1,%2,%3};"
                 : "+f"(d[0]), "+f"(d[1]), "+f"(d[2]), "+f"(d[3])
                 : "r"(a[0]), "r"(a[1]), "r"(a[2]), "r"(a[3]),
                   "r"(b[0]), "r"(b[1]));
}
__device__ __forceinline__ uint32_t pack_bf2(__nv_bfloat16 lo, __nv_bfloat16 hi) {
    return ((uint32_t)__bfloat16_as_ushort(hi) << 16) | __bfloat16_as_ushort(lo);
}

// ===================== fused converts + mask probe =====================
// rows: [0,2048) x->Ax (A-split), [2048,2560) q_w->Bqkv, [2560,3584) kv_w->Bqkv+512,
// [3584,4096) proj_w->Bproj. Block 4096 = mask probe.
__global__ __launch_bounds__(128) void convert_all_kernel(
    const float* __restrict__ x, const float* __restrict__ q_w,
    const float* __restrict__ kv_w, const float* __restrict__ proj_w,
    const void* __restrict__ mask,
    __nv_bfloat16* __restrict__ Ax, __nv_bfloat16* __restrict__ Bqkv,
    __nv_bfloat16* __restrict__ Bproj)
{
    const int rb = blockIdx.x;
    if (rb == 4096) {
        __shared__ int s_not_i32, s_not_f32;
        if (threadIdx.x == 0) { s_not_i32 = 0; s_not_f32 = 0; }
        __syncthreads();
        const unsigned int* w = (const unsigned int*)mask;
        int bad_i = 0, bad_f = 0;
        for (int i = threadIdx.x; i < 544; i += 128) {
            unsigned int v = w[i];
            if (v > 1u) bad_i = 1;
            if (v != 0u && v != 0x3F800000u) bad_f = 1;
        }
        if (bad_i) atomicOr(&s_not_i32, 1);
        if (bad_f) atomicOr(&s_not_f32, 1);
        __syncthreads();
        if (threadIdx.x == 0)
            g_mask_mode = (!s_not_i32) ? 0 : ((!s_not_f32) ? 1 : 2);
        return;
    }
    const float* src;
    __nv_bfloat16* dst;
    bool aSide;
    if (rb < 2048)      { src = x + (size_t)rb * kC;            dst = Ax + (size_t)rb * kKp;            aSide = true;  }
    else if (rb < 2560) { int r = rb - 2048; src = q_w + (size_t)r * kC;   dst = Bqkv + (size_t)r * kKp;         aSide = false; }
    else if (rb < 3584) { int r = rb - 2560; src = kv_w + (size_t)r * kC;  dst = Bqkv + (size_t)(kC + r) * kKp;  aSide = false; }
    else                { int r = rb - 3584; src = proj_w + (size_t)r * kC; dst = Bproj + (size_t)r * kKp;       aSide = false; }

    const int j0 = threadIdx.x * 4;
    float4 v = *(const float4*)&src[j0];
    float f[4] = {v.x, v.y, v.z, v.w};
    __nv_bfloat16 hi[4], lo[4];
#pragma unroll
    for (int t = 0; t < 4; t++) {
        hi[t] = __float2bfloat16(f[t]);
        lo[t] = __float2bfloat16(f[t] - __bfloat162float(hi[t]));
    }
    uint32_t hp0 = pack_bf2(hi[0], hi[1]), hp1 = pack_bf2(hi[2], hi[3]);
    uint32_t lp0 = pack_bf2(lo[0], lo[1]), lp1 = pack_bf2(lo[2], lo[3]);
    uint32_t* d0 = (uint32_t*)(dst + j0);
    uint32_t* d1 = (uint32_t*)(dst + kC + j0);
    uint32_t* d2 = (uint32_t*)(dst + 2 * kC + j0);
    d0[0] = hp0; d0[1] = hp1;
    if (aSide) { d1[0] = lp0; d1[1] = lp1; d2[0] = hp0; d2[1] = hp1; }
    else       { d1[0] = hp0; d1[1] = hp1; d2[0] = lp0; d2[1] = lp1; }
}

// O -> AO (A-split), vectorized
__global__ __launch_bounds__(128) void convert_aO_kernel(
    const float* __restrict__ src0, __nv_bfloat16* __restrict__ dst0)
{
    const int rb = blockIdx.x;
    const float* src = src0 + (size_t)rb * kC;
    __nv_bfloat16* dst = dst0 + (size_t)rb * kKp;
    const int j0 = threadIdx.x * 4;
    float4 v = *(const float4*)&src[j0];
    float f[4] = {v.x, v.y, v.z, v.w};
    __nv_bfloat16 hi[4], lo[4];
#pragma unroll
    for (int t = 0; t < 4; t++) {
        hi[t] = __float2bfloat16(f[t]);
        lo[t] = __float2bfloat16(f[t] - __bfloat162float(hi[t]));
    }
    uint32_t hp0 = pack_bf2(hi[0], hi[1]), hp1 = pack_bf2(hi[2], hi[3]);
    uint32_t lp0 = pack_bf2(lo[0], lo[1]), lp1 = pack_bf2(lo[2], lo[3]);
    uint32_t* d0 = (uint32_t*)(dst + j0);
    uint32_t* d1 = (uint32_t*)(dst + kC + j0);
    uint32_t* d2 = (uint32_t*)(dst + 2 * kC + j0);
    d0[0] = hp0; d0[1] = hp1;
    d1[0] = lp0; d1[1] = lp1;
    d2[0] = hp0; d2[1] = hp1;
}

// ===================== templated mma.sync bf16 GEMM =====================
// MODE 0: C = A@B^T (+bias), split columns C0/C1 (fp32 out)
// MODE 1: qkv epilogue -> qbf (hi|lo|hi), kbf (hi|hi|lo), yv fp32
// MODE 2: per-(b,h) qk: S = 0.125 * q@k^T, blockIdx.x = bh
template<int KBYTES, int NITER, int MODE>
__global__ __launch_bounds__(256) void mma_gemm_t(
    const __nv_bfloat16* __restrict__ A,
    const __nv_bfloat16* __restrict__ Bw,
    float* __restrict__ C0, float* __restrict__ C1,
    const float* __restrict__ bias, int split, int ld0, int ld1,
    __nv_bfloat16* __restrict__ qbf, __nv_bfloat16* __restrict__ kbf,
    float* __restrict__ yv)
{
    __shared__ __align__(16) char smem[2][16384];
    const int tid = threadIdx.x;
    const int wid = tid >> 5, lane = tid & 31;
    const int warp_m = wid >> 1, warp_n = wid & 1;

    int m0, n0;
    const char *Ag, *Bg;
    if (MODE == 2) {
        const size_t off = (size_t)blockIdx.x * 128 * KBYTES;
        Ag = (const char*)A + off;
        Bg = (const char*)Bw + off;
        m0 = 0; n0 = 0;
    } else {
        m0 = blockIdx.y * 128; n0 = blockIdx.x * 128;
        Ag = (const char*)A  + (size_t)m0 * KBYTES;
        Bg = (const char*)Bw + (size_t)n0 * KBYTES;
    }

    const int lr = tid >> 2, lc = tid & 3;
    const uint32_t lso  = (uint32_t)(lr * 64 + ((lc ^ (lr & 3)) << 4));
    const uint32_t lso2 = (uint32_t)((lr + 64) * 64 + ((lc ^ ((lr + 64) & 3)) << 4));
    uint32_t sbase = smem_u32(&smem[0][0]);

    auto stage_load = [&](int st, int k0b) {
        uint32_t sA = sbase + st * 16384;
        uint32_t sB = sA + 8192;
        const char* a0 = Ag + (size_t)lr * KBYTES + k0b + lc * 16;
        const char* b0 = Bg + (size_t)lr * KBYTES + k0b + lc * 16;
        cp_async16(sA + lso,  a0);
        cp_async16(sB + lso,  b0);
        cp_async16(sA + lso2, a0 + (size_t)64 * KBYTES);
        cp_async16(sB + lso2, b0 + (size_t)64 * KBYTES);
    };

    float acc[2][8][4];
#pragma unroll
    for (int i = 0; i < 2; i++)
#pragma unroll
        for (int j = 0; j < 8; j++)
#pragma unroll
            for (int t = 0; t < 4; t++) acc[i][j][t] = 0.f;

    stage_load(0, 0);
    cp_commit();

    const int a_row = warp_m * 32 + (lane & 15);
    const int a_chsel = lane >> 4;
    const int b_mi = lane >> 3;
    const int b_row = warp_n * 64 + ((b_mi >> 1) << 3) + (lane & 7);
    const int b_chsel = b_mi & 1;

    for (int it = 0; it < NITER; it++) {
        cp_wait0();
        __syncthreads();
        if (it + 1 < NITER) { stage_load((it + 1) & 1, (it + 1) * 64); cp_commit(); }

        const uint32_t sA = sbase + (it & 1) * 16384;
        const uint32_t sB = sA + 8192;
#pragma unroll
        for (int kk = 0; kk < 2; kk++) {
            uint32_t a[2][4];
#pragma unroll
            for (int i = 0; i < 2; i++) {
                int r = a_row + i * 16;
                int ch = 2 * kk + a_chsel;
                ldsm_x4(a[i], sA + r * 64 + ((ch ^ (r & 3)) << 4));
            }
            uint32_t b[8][2];
#pragma unroll
            for (int g = 0; g < 4; g++) {
                int r = b_row + g * 16;
                int ch = 2 * kk + b_chsel;
                uint32_t rr[4];
                ldsm_x4(rr, sB + r * 64 + ((ch ^ (r & 3)) << 4));
                b[2 * g][0] = rr[0]; b[2 * g][1] = rr[1];
                b[2 * g + 1][0] = rr[2]; b[2 * g + 1][1] = rr[3];
            }
#pragma unroll
            for (int i = 0; i < 2; i++)
#pragma unroll
                for (int j = 0; j < 8; j++)
                    mma16816(acc[i][j], a[i], b[j]);
        }
        __syncthreads();
    }

    const int gq = lane >> 2, t4 = lane & 3;

    if (MODE == 2) {
        float* Sp = C0 + (size_t)blockIdx.x * kN * kN;
#pragma unroll
        for (int i = 0; i < 2; i++) {
#pragma unroll
            for (int j = 0; j < 8; j++) {
                int col = warp_n * 64 + j * 8 + t4 * 2;
                int r0 = warp_m * 32 + i * 16 + gq;
                *(float2*)&Sp[(size_t)r0 * kN + col] =
                    make_float2(acc[i][j][0] * 0.125f, acc[i][j][1] * 0.125f);
                *(float2*)&Sp[(size_t)(r0 + 8) * kN + col] =
                    make_float2(acc[i][j][2] * 0.125f, acc[i][j][3] * 0.125f);
            }
        }
        return;
    }

    if (MODE == 1) {
        auto emit = [&](int row, int colg, float f0, float f1) {
            if (colg < 1024) {
                const bool isQ = colg < 512;
                const int c = isQ ? colg : colg - 512;
                const int h = c >> 6, d = c & 63;
                __nv_bfloat16 h0 = __float2bfloat16(f0);
                __nv_bfloat16 h1 = __float2bfloat16(f1);
                __nv_bfloat16 l0 = __float2bfloat16(f0 - __bfloat162float(h0));
                __nv_bfloat16 l1 = __float2bfloat16(f1 - __bfloat162float(h1));
                uint32_t hp = pack_bf2(h0, h1);
                uint32_t lp = pack_bf2(l0, l1);
                const int bb = row >> 7, nn = row & 127;
                __nv_bfloat16* base = (isQ ? qbf : kbf)
                    + ((size_t)((bb * kH + h) * kN + nn)) * kKq + d;
                *(uint32_t*)(base)       = hp;
                *(uint32_t*)(base + 64)  = isQ ? lp : hp;
                *(uint32_t*)(base + 128) = isQ ? hp : lp;
            } else {
                *(float2*)&yv[(size_t)row * kC + (colg - 1024)] = make_float2(f0, f1);
            }
        };
#pragma unroll
        for (int i = 0; i < 2; i++) {
#pragma unroll
            for (int j = 0; j < 8; j++) {
                int colg = n0 + warp_n * 64 + j * 8 + t4 * 2;
                int row0 = m0 + warp_m * 32 + i * 16 + gq;
                emit(row0,     colg, acc[i][j][0], acc[i][j][1]);
                emit(row0 + 8, colg, acc[i][j][2], acc[i][j][3]);
            }
        }
        return;
    }

    // MODE 0
#pragma unroll
    for (int i = 0; i < 2; i++) {
#pragma unroll
        for (int j = 0; j < 8; j++) {
            int colg = n0 + warp_n * 64 + j * 8 + t4 * 2;
            float bz0 = bias ? bias[colg]     : 0.f;
            float bz1 = bias ? bias[colg + 1] : 0.f;
            float* Cc; int ldc, cc;
            if (colg < split) { Cc = C0; ldc = ld0; cc = colg; }
            else              { Cc = C1; ldc = ld1; cc = colg - split; }
            int row0 = m0 + warp_m * 32 + i * 16 + gq;
            *(float2*)&Cc[(size_t)row0 * ldc + cc] =
                make_float2(acc[i][j][0] + bz0, acc[i][j][1] + bz1);
            *(float2*)&Cc[(size_t)(row0 + 8) * ldc + cc] =
                make_float2(acc[i][j][2] + bz0, acc[i][j][3] + bz1);
        }
    }
}

// ===================== att: logits + softmax + W = P@A =====================
__global__ __launch_bounds__(256) void att_kernel(
    const float* __restrict__ S, const float* __restrict__ assign,
    const void* __restrict__ mask, const float* __restrict__ rel_bias,
    float* __restrict__ Wout)
{
    const int bn = blockIdx.x;
    const int b = bn >> 7, n = bn & 127;
    __shared__ float As[kN * kR];
    __shared__ float Ss[kH * kN];
    __shared__ float Ls[kH][kR];
    __shared__ float Ps[kH][kR];
    const int tid = threadIdx.x;

    const float* arow = assign + (size_t)n * kN * kR;
    for (int i = tid; i < kN * kR; i += 256) As[i] = arow[i];
    for (int i = tid; i < kH * kN; i += 256) {
        int h = i >> 7, m = i & 127;
        Ss[i] = S[(((size_t)(b * kH + h)) * kN + n) * kN + m];
    }
    __syncthreads();

    if (tid < kH * kR) {
        int h = tid / kR, r = tid % kR;
        float acc = 0.f;
#pragma unroll 4
        for (int m = 0; m < kN; m++) acc += As[m * kR + r] * Ss[h * kN + m];
        acc += rel_bias[h * kR + r];
        int mode = g_mask_mode;
        int idx = n * kR + r;
        bool msk;
        if (mode == 0)      msk = ((const int*)mask)[idx] != 0;
        else if (mode == 1) msk = ((const float*)mask)[idx] != 0.f;
        else                msk = ((const unsigned char*)mask)[idx] != 0;
        Ls[h][r] = msk ? neg_inf() : acc;
    }
    __syncthreads();

    if (tid < kH) {
        int h = tid;
        float mx = neg_inf();
#pragma unroll
        for (int r = 0; r < kR; r++) mx = fmaxf(mx, Ls[h][r]);
        float s = 0.f;
#pragma unroll
        for (int r = 0; r < kR; r++) { float e = __expf(Ls[h][r] - mx); Ps[h][r] = e; s += e; }
        float inv = 1.f / s;
#pragma unroll
        for (int r = 0; r < kR; r++) Ps[h][r] *= inv;
    }
    __syncthreads();

    for (int i = tid; i < kH * kN; i += 256) {
        int h = i >> 7, m = i & 127;
        float acc = 0.f;
#pragma unroll
        for (int r = 0; r < kR; r++) acc += Ps[h][r] * As[m * kR + r];
        Wout[(((size_t)(b * kH + h)) * kN + n) * kN + m] = acc;
    }
}

// ===================== av: O[b,n,h,d] = W @ yv =====================
__global__ __launch_bounds__(256) void av_kernel(
    const float* __restrict__ Wg, const float* __restrict__ yv,
    float* __restrict__ O)
{
    const int bh = blockIdx.x;
    const int b = bh >> 3, h = bh & 7;
    __shared__ float ws[32][128];
    __shared__ float vs[32][64];
    const int tid = threadIdx.x;
    const int tx = tid & 15, ty = tid >> 4;

    float acc[8][4];
#pragma unroll
    for (int i = 0; i < 8; i++)
#pragma unroll
        for (int j = 0; j < 4; j++) acc[i][j] = 0.f;

    const float* Wb = Wg + (size_t)bh * kN * kN;
    const float* vbase = yv + (size_t)b * kN * kC + h * kHD;

    for (int m0 = 0; m0 < kN; m0 += 32) {
#pragma unroll
        for (int p = 0; p < 4; p++) {
            int f = tid + p * 256;
            int nrow = f >> 3;
            int mc = (f & 7) * 4;
            float4 v = *(const float4*)&Wb[(size_t)nrow * kN + m0 + mc];
            ws[mc + 0][nrow] = v.x; ws[mc + 1][nrow] = v.y;
            ws[mc + 2][nrow] = v.z; ws[mc + 3][nrow] = v.w;
        }
#pragma unroll
        for (int p = 0; p < 2; p++) {
            int f = tid + p * 256;
            int mrow = f >> 4;
            int dd = (f & 15) * 4;
            float4 v = *(const float4*)&vbase[(size_t)(m0 + mrow) * kC + dd];
            *(float4*)&vs[mrow][dd] = v;
        }
        __syncthreads();
#pragma unroll
        for (int k = 0; k < 32; k++) {
            float a[8], bb[4];
            *(float4*)&a[0]  = *(const float4*)&ws[k][ty * 8];
            *(float4*)&a[4]  = *(const float4*)&ws[k][ty * 8 + 4];
            *(float4*)&bb[0] = *(const float4*)&vs[k][tx * 4];
#pragma unroll
            for (int i = 0; i < 8; i++)
#pragma unroll
                for (int j = 0; j < 4; j++) acc[i][j] += a[i] * bb[j];
        }
        __syncthreads();
    }

#pragma unroll
    for (int i = 0; i < 8; i++) {
        int n = ty * 8 + i;
        float4 o = make_float4(acc[i][0], acc[i][1], acc[i][2], acc[i][3]);
        *(float4*)&O[((size_t)(b * kN + n)) * kC + h * kHD + tx * 4] = o;
    }
}

// ===================== launch =====================
extern "C" void kernel_launch(void* const* d_in, const int* in_sizes, int n_in,
                              void* d_out, int out_size)
{
    const float* x        = (const float*)d_in[0];
    const float* assign   = (const float*)d_in[1];
    const void*  mask     = d_in[2];
    const float* q_w      = (const float*)d_in[3];
    const float* kv_w     = (const float*)d_in[4];
    const float* rel_bias = (const float*)d_in[5];
    const float* proj_w   = (const float*)d_in[6];
    const float* proj_b   = (const float*)d_in[7];

    float *S, *Wg, *O, *yv;
    __nv_bfloat16 *Ax, *Bqkv, *Bproj, *AO, *qbf, *kbf;
    cudaGetSymbolAddress((void**)&S,   g_S);
    cudaGetSymbolAddress((void**)&Wg,  g_W);
    cudaGetSymbolAddress((void**)&O,   g_O);
    cudaGetSymbolAddress((void**)&yv,  g_yv);
    cudaGetSymbolAddress((void**)&Ax,    g_Ax);
    cudaGetSymbolAddress((void**)&Bqkv,  g_Bqkv);
    cudaGetSymbolAddress((void**)&Bproj, g_Bproj);
    cudaGetSymbolAddress((void**)&AO,    g_AO);
    cudaGetSymbolAddress((void**)&qbf,   g_qbf);
    cudaGetSymbolAddress((void**)&kbf,   g_kbf);

    // 1. all input hi/lo splits + mask probe
    convert_all_kernel<<<4097, 128>>>(x, q_w, kv_w, proj_w, mask, Ax, Bqkv, Bproj);

    // 2. fused q/kv projection -> qbf/kbf (bf16 hi-lo) + yv (fp32)
    mma_gemm_t<3072, 48, 1><<<dim3(12, 16), 256>>>(
        Ax, Bqkv, nullptr, nullptr, nullptr, 0, 0, 0, qbf, kbf, yv);

    // 3. S = 0.125 * q@k^T per (b,h) on tensor cores
    mma_gemm_t<384, 6, 2><<<dim3(128, 1), 256>>>(
        qbf, kbf, S, nullptr, nullptr, 0, 0, 0, nullptr, nullptr, nullptr);

    // 4. logits + masked softmax + W = P@A
    att_kernel<<<kB * kN, 256>>>(S, assign, mask, rel_bias, Wg);

    // 5. O = W @ yv
    av_kernel<<<kB * kH, 256>>>(Wg, yv, O);

    // 6-7. out-proj
    convert_aO_kernel<<<kBN, 128>>>(O, AO);
    mma_gemm_t<3072, 48, 0><<<dim3(4, 16), 256>>>(
        AO, Bproj, (float*)d_out, (float*)d_out, proj_b, 1 << 30, kC, kC,
        nullptr, nullptr, nullptr);
}